// round 8
// baseline (speedup 1.0000x reference)
#include <cuda_runtime.h>
#include <cuda_bf16.h>
#include <math.h>

#define THREADS 256
#define WARPS 8
#define CTAS 296

// dynamic smem byte offsets
#define OFF_TAB 0                        // 8192 bf16x2 words            (32768 B)
#define OFF_W1T 32768                    // [n=64][8w] pair layout        (2048 B)
#define OFF_R1T (OFF_W1T + 2048)         // same                          (2048 B)
#define OFF_W2T (OFF_R1T + 2048)         // [n=16][40w] pair layout       (2560 B)
#define OFF_R2T (OFF_W2T + 2560)         // [n=64][40w]                  (10240 B)
#define OFF_R3T (OFF_R2T + 10240)        // [n= 8][40w]                   (1280 B)
#define OFF_STG (OFF_R3T + 1280)         // per warp: 8 kpairs * 40 words (1280 B)
#define SMEM_BYTES (OFF_STG + WARPS * 1280)   // 61184 B

__device__ __forceinline__ unsigned pack_bf16(float lo, float hi) {
    unsigned d;
    asm("cvt.rn.bf16x2.f32 %0, %1, %2;" : "=r"(d) : "f"(hi), "f"(lo));
    return d;
}
__device__ __forceinline__ unsigned packrelu(float a, float b) {
    unsigned d = pack_bf16(a, b);
    __nv_bfloat162 z = __float2bfloat162_rn(0.f);
    __nv_bfloat162 v = __hmax2(*(__nv_bfloat162*)&d, z);
    return *(unsigned*)&v;
}
__device__ __forceinline__ void mma_bf16(float* c, const unsigned* a,
                                         unsigned b0, unsigned b1) {
    asm volatile(
        "mma.sync.aligned.m16n8k16.row.col.f32.bf16.bf16.f32 "
        "{%0,%1,%2,%3}, {%4,%5,%6,%7}, {%8,%9}, {%0,%1,%2,%3};\n"
        : "+f"(c[0]), "+f"(c[1]), "+f"(c[2]), "+f"(c[3])
        : "r"(a[0]), "r"(a[1]), "r"(a[2]), "r"(a[3]), "r"(b0), "r"(b1));
}
__device__ __forceinline__ float ldg_nc(const float* p) {
    float v;
    asm("ld.global.nc.f32 %0, [%1];" : "=f"(v) : "l"(p));
    return v;
}

// element index for k16 pair layout (w1t/r1t): word = n*8 + tig*2 + j
__device__ __forceinline__ int e_k16(int n, int k) {
    int tig = (k >> 1) & 3, j = (k >> 3) & 1;
    return (n * 8 + tig * 2 + j) * 2 + (k & 1);
}
// element index for k64 pair layout (w2t/r2t/r3t): word = n*40 + kc*8 + tig*2 + j
__device__ __forceinline__ int e_k64(int n, int k) {
    int kc = k >> 4, kk = k & 15;
    int tig = (kk >> 1) & 3, j = (kk >> 3) & 1;
    return (n * 40 + kc * 8 + tig * 2 + j) * 2 + (k & 1);
}

__global__ __launch_bounds__(THREADS, 2) void ngp_mma_kernel(
    const float* __restrict__ x,
    const float* __restrict__ table,
    const float* __restrict__ w1,
    const float* __restrict__ w2,
    const float* __restrict__ r1,
    const float* __restrict__ r2,
    const float* __restrict__ r3,
    float* __restrict__ out,
    int N, int4 ra, int4 rb)
{
    extern __shared__ char sm[];
    unsigned* s_tab = (unsigned*)(sm + OFF_TAB);       // bf16x2 per entry
    __nv_bfloat16* w1t = (__nv_bfloat16*)(sm + OFF_W1T);
    __nv_bfloat16* r1t = (__nv_bfloat16*)(sm + OFF_R1T);
    __nv_bfloat16* w2t = (__nv_bfloat16*)(sm + OFF_W2T);
    __nv_bfloat16* r2t = (__nv_bfloat16*)(sm + OFF_R2T);
    __nv_bfloat16* r3t = (__nv_bfloat16*)(sm + OFF_R3T);
    const unsigned* w1t_w = (const unsigned*)w1t;
    const unsigned* r1t_w = (const unsigned*)r1t;
    const unsigned* w2t_w = (const unsigned*)w2t;
    const unsigned* r2t_w = (const unsigned*)r2t;
    const unsigned* r3t_w = (const unsigned*)r3t;

    const int tid = threadIdx.x;
    for (int i = tid; i < 8192; i += THREADS) {
        float2 t = ((const float2*)table)[i];
        s_tab[i] = pack_bf16(t.x, t.y);
    }
    for (int i = tid; i < 1024; i += THREADS) {
        int n = i >> 4, k = i & 15;
        int e = e_k16(n, k);
        w1t[e] = __float2bfloat16(w1[k * 64 + n]);
        r1t[e] = __float2bfloat16(r1[k * 64 + n]);
    }
    for (int i = tid; i < 1024; i += THREADS) {
        int n = i >> 6, k = i & 63;
        w2t[e_k64(n, k)] = __float2bfloat16(w2[k * 16 + n]);
    }
    for (int i = tid; i < 4096; i += THREADS) {
        int n = i >> 6, k = i & 63;
        r2t[e_k64(n, k)] = __float2bfloat16(r2[k * 64 + n]);
    }
    for (int i = tid; i < 640; i += THREADS) {   // 8 rows * 40 words * 2 elems
        int word = i >> 1;
        int n = word / 40, rem = word % 40;
        int kc = rem >> 3, tig = (rem >> 1) & 3, j = rem & 1;
        int k = kc * 16 + j * 8 + tig * 2 + (i & 1);
        r3t[i] = __float2bfloat16((n == 0 && rem < 32) ? r3[k] : 0.f);
    }
    __syncthreads();

    const int res[8] = {ra.x, ra.y, ra.z, ra.w, rb.x, rb.y, rb.z, rb.w};

    const int warp = tid >> 5, lane = tid & 31;
    const int g = lane >> 2, tig = lane & 3;
    unsigned* stg = (unsigned*)(sm + OFF_STG) + warp * 320;  // 8 kpairs x 40 words

    const int gw = blockIdx.x * WARPS + warp;
    const int stride = CTAS * WARPS * 32;

    // ---- software-pipelined point coords ----
    int p = gw * 32 + lane;
    float cx = 0.f, cy = 0.f, cz = 0.f;
    if (p < N) {
        cx = ldg_nc(x + 3 * p)     + 0.5f;
        cy = ldg_nc(x + 3 * p + 1) + 0.5f;
        cz = ldg_nc(x + 3 * p + 2) + 0.5f;
    }

    for (int base = gw * 32; base < N; base += stride) {
        __syncwarp();
        // ------------ hash-grid encode: one point per lane ------------
        unsigned hfp[8];
        {
            float x01 = cx, y01 = cy, z01 = cz;
            #pragma unroll
            for (int l = 0; l < 8; l++) {
                float rf = (float)res[l];
                float fx = x01 * rf, fy = y01 * rf, fz = z01 * rf;
                float gx = floorf(fx), gy = floorf(fy), gz = floorf(fz);
                float wx = fx - gx, wy = fy - gy, wz = fz - gz;
                unsigned ix = (unsigned)(int)gx;
                unsigned iy = (unsigned)(int)gy;
                unsigned iz = (unsigned)(int)gz;
                unsigned hx0 = ix, hx1 = ix + 1u;
                unsigned hy0 = iy * 2654435761u, hy1 = hy0 + 2654435761u;
                unsigned hz0 = iz * 805459861u,  hz1 = hz0 + 805459861u;
                float wx0 = 1.f - wx, wy0 = 1.f - wy, wz0 = 1.f - wz;
                float w00 = wx0 * wy0, w01 = wx0 * wy;
                float w10 = wx * wy0,  w11 = wx * wy;
                const unsigned* tl = s_tab + l * 1024;
                __nv_bfloat162 acc0 = __floats2bfloat162_rn(0.f, 0.f);
                __nv_bfloat162 acc1 = acc0;
                #pragma unroll
                for (int c = 0; c < 8; c += 2) {
                    unsigned hbase = ((c & 4) ? hx1 : hx0)
                                   ^ ((c & 2) ? hy1 : hy0);
                    float wxy = (c & 4) ? ((c & 2) ? w11 : w10)
                                        : ((c & 2) ? w01 : w00);
                    unsigned idx0 = (hbase ^ hz0) & 1023u;
                    unsigned idx1 = (hbase ^ hz1) & 1023u;
                    float wgt0 = wxy * wz0;
                    float wgt1 = wxy * wz;
                    unsigned wd0 = pack_bf16(wgt0, wgt0);
                    unsigned wd1 = pack_bf16(wgt1, wgt1);
                    unsigned td0 = tl[idx0];
                    unsigned td1 = tl[idx1];
                    acc0 = __hfma2(*(__nv_bfloat162*)&wd0, *(__nv_bfloat162*)&td0, acc0);
                    acc1 = __hfma2(*(__nv_bfloat162*)&wd1, *(__nv_bfloat162*)&td1, acc1);
                }
                __nv_bfloat162 acc = __hadd2(acc0, acc1);
                hfp[l] = *(unsigned*)&acc;
            }
        }
        #pragma unroll
        for (int kp = 0; kp < 8; kp++)
            stg[kp * 40 + lane] = hfp[kp];
        __syncwarp();

        // ------------ A0 fragments for both 16-point chains ------------
        unsigned A0h0[4], A0h1[4];
        A0h0[0] = stg[tig * 40 + g];
        A0h0[1] = stg[tig * 40 + g + 8];
        A0h0[2] = stg[(tig + 4) * 40 + g];
        A0h0[3] = stg[(tig + 4) * 40 + g + 8];
        A0h1[0] = stg[tig * 40 + 16 + g];
        A0h1[1] = stg[tig * 40 + 16 + g + 8];
        A0h1[2] = stg[(tig + 4) * 40 + 16 + g];
        A0h1[3] = stg[(tig + 4) * 40 + 16 + g + 8];

        // ------------ prefetch next iteration's coords (hide DRAM latency
        // behind the whole MMA/epilogue section) ------------
        p += stride;
        if (p < N) {
            cx = ldg_nc(x + 3 * p)     + 0.5f;
            cy = ldg_nc(x + 3 * p + 1) + 0.5f;
            cz = ldg_nc(x + 3 * p + 2) + 0.5f;
        } else {
            cx = cy = cz = 0.f;
        }

        // ------------ L1: 16 -> 64, relu (B shared across chains) ------------
        unsigned A1h0[16], A1h1[16];
        #pragma unroll
        for (int cp = 0; cp < 4; cp++) {
            float Ca0[4] = {0,0,0,0}, Ca1[4] = {0,0,0,0};
            float Cb0[4] = {0,0,0,0}, Cb1[4] = {0,0,0,0};
            int na = 16 * cp + g, nb = na + 8;
            uint2 ba = *(const uint2*)(w1t_w + na * 8 + tig * 2);
            uint2 bb = *(const uint2*)(w1t_w + nb * 8 + tig * 2);
            mma_bf16(Ca0, A0h0, ba.x, ba.y);
            mma_bf16(Ca1, A0h1, ba.x, ba.y);
            mma_bf16(Cb0, A0h0, bb.x, bb.y);
            mma_bf16(Cb1, A0h1, bb.x, bb.y);
            A1h0[cp*4+0] = packrelu(Ca0[0], Ca0[1]);
            A1h0[cp*4+1] = packrelu(Ca0[2], Ca0[3]);
            A1h0[cp*4+2] = packrelu(Cb0[0], Cb0[1]);
            A1h0[cp*4+3] = packrelu(Cb0[2], Cb0[3]);
            A1h1[cp*4+0] = packrelu(Ca1[0], Ca1[1]);
            A1h1[cp*4+1] = packrelu(Ca1[2], Ca1[3]);
            A1h1[cp*4+2] = packrelu(Cb1[0], Cb1[1]);
            A1h1[cp*4+3] = packrelu(Cb1[2], Cb1[3]);
        }

        // ------------ L2: 64 -> 16, linear ------------
        unsigned A2h0[4], A2h1[4];
        {
            float C0h0[4] = {0,0,0,0}, C0h1[4] = {0,0,0,0};
            float C1h0[4] = {0,0,0,0}, C1h1[4] = {0,0,0,0};
            #pragma unroll
            for (int kc = 0; kc < 4; kc++) {
                uint2 b0 = *(const uint2*)(w2t_w + g * 40 + kc * 8 + tig * 2);
                uint2 b1 = *(const uint2*)(w2t_w + (8 + g) * 40 + kc * 8 + tig * 2);
                mma_bf16(C0h0, &A1h0[kc*4], b0.x, b0.y);
                mma_bf16(C0h1, &A1h1[kc*4], b0.x, b0.y);
                mma_bf16(C1h0, &A1h0[kc*4], b1.x, b1.y);
                mma_bf16(C1h1, &A1h1[kc*4], b1.x, b1.y);
            }
            A2h0[0] = pack_bf16(C0h0[0], C0h0[1]);
            A2h0[1] = pack_bf16(C0h0[2], C0h0[3]);
            A2h0[2] = pack_bf16(C1h0[0], C1h0[1]);
            A2h0[3] = pack_bf16(C1h0[2], C1h0[3]);
            A2h1[0] = pack_bf16(C0h1[0], C0h1[1]);
            A2h1[1] = pack_bf16(C0h1[2], C0h1[3]);
            A2h1[2] = pack_bf16(C1h1[0], C1h1[1]);
            A2h1[3] = pack_bf16(C1h1[2], C1h1[3]);
        }

        // ------------ L3: 16 -> 64, relu ------------
        unsigned A3h0[16], A3h1[16];
        #pragma unroll
        for (int cp = 0; cp < 4; cp++) {
            float Ca0[4] = {0,0,0,0}, Ca1[4] = {0,0,0,0};
            float Cb0[4] = {0,0,0,0}, Cb1[4] = {0,0,0,0};
            int na = 16 * cp + g, nb = na + 8;
            uint2 ba = *(const uint2*)(r1t_w + na * 8 + tig * 2);
            uint2 bb = *(const uint2*)(r1t_w + nb * 8 + tig * 2);
            mma_bf16(Ca0, A2h0, ba.x, ba.y);
            mma_bf16(Ca1, A2h1, ba.x, ba.y);
            mma_bf16(Cb0, A2h0, bb.x, bb.y);
            mma_bf16(Cb1, A2h1, bb.x, bb.y);
            A3h0[cp*4+0] = packrelu(Ca0[0], Ca0[1]);
            A3h0[cp*4+1] = packrelu(Ca0[2], Ca0[3]);
            A3h0[cp*4+2] = packrelu(Cb0[0], Cb0[1]);
            A3h0[cp*4+3] = packrelu(Cb0[2], Cb0[3]);
            A3h1[cp*4+0] = packrelu(Ca1[0], Ca1[1]);
            A3h1[cp*4+1] = packrelu(Ca1[2], Ca1[3]);
            A3h1[cp*4+2] = packrelu(Cb1[0], Cb1[1]);
            A3h1[cp*4+3] = packrelu(Cb1[2], Cb1[3]);
        }

        // ------------ L4: 64 -> 64, relu ------------
        unsigned Gh0[16], Gh1[16];
        #pragma unroll
        for (int cp = 0; cp < 4; cp++) {
            float Ca0[4] = {0,0,0,0}, Ca1[4] = {0,0,0,0};
            float Cb0[4] = {0,0,0,0}, Cb1[4] = {0,0,0,0};
            int na = 16 * cp + g, nb = na + 8;
            #pragma unroll
            for (int kc = 0; kc < 4; kc++) {
                uint2 ba = *(const uint2*)(r2t_w + na * 40 + kc * 8 + tig * 2);
                uint2 bb = *(const uint2*)(r2t_w + nb * 40 + kc * 8 + tig * 2);
                mma_bf16(Ca0, &A3h0[kc*4], ba.x, ba.y);
                mma_bf16(Ca1, &A3h1[kc*4], ba.x, ba.y);
                mma_bf16(Cb0, &A3h0[kc*4], bb.x, bb.y);
                mma_bf16(Cb1, &A3h1[kc*4], bb.x, bb.y);
            }
            Gh0[cp*4+0] = packrelu(Ca0[0], Ca0[1]);
            Gh0[cp*4+1] = packrelu(Ca0[2], Ca0[3]);
            Gh0[cp*4+2] = packrelu(Cb0[0], Cb0[1]);
            Gh0[cp*4+3] = packrelu(Cb0[2], Cb0[3]);
            Gh1[cp*4+0] = packrelu(Ca1[0], Ca1[1]);
            Gh1[cp*4+1] = packrelu(Ca1[2], Ca1[3]);
            Gh1[cp*4+2] = packrelu(Cb1[0], Cb1[1]);
            Gh1[cp*4+3] = packrelu(Cb1[2], Cb1[3]);
        }

        // ------------ L5: 64 -> 1 (+sigmoid) ------------
        float C5h0[4] = {0,0,0,0}, C5h1[4] = {0,0,0,0};
        #pragma unroll
        for (int kc = 0; kc < 4; kc++) {
            uint2 b = *(const uint2*)(r3t_w + g * 40 + kc * 8 + tig * 2);
            mma_bf16(C5h0, &Gh0[kc*4], b.x, b.y);
            mma_bf16(C5h1, &Gh1[kc*4], b.x, b.y);
        }
        if (tig == 0) {
            int o = base + g;
            if (o < N)      out[o]      = 1.f / (1.f + __expf(-C5h0[0]));
            if (o + 8 < N)  out[o + 8]  = 1.f / (1.f + __expf(-C5h0[2]));
            if (o + 16 < N) out[o + 16] = 1.f / (1.f + __expf(-C5h1[0]));
            if (o + 24 < N) out[o + 24] = 1.f / (1.f + __expf(-C5h1[2]));
        }
    }
}

extern "C" void kernel_launch(void* const* d_in, const int* in_sizes, int n_in,
                              void* d_out, int out_size) {
    const float* x     = (const float*)d_in[0];
    const float* table = (const float*)d_in[1];
    const float* w1    = (const float*)d_in[2];
    const float* w2    = (const float*)d_in[3];
    const float* r1    = (const float*)d_in[4];
    const float* r2    = (const float*)d_in[5];
    const float* r3    = (const float*)d_in[6];
    float* out = (float*)d_out;
    int N = in_sizes[0] / 3;

    // Replicate numpy's RES computation with host libm (RES[7] sits at 10-1e-14).
    double b = exp(log(5.0) / 7.0);
    int rs[8];
    for (int l = 0; l < 8; l++) rs[l] = (int)floor(2.0 * pow(b, (double)l));
    int4 ra = make_int4(rs[0], rs[1], rs[2], rs[3]);
    int4 rb = make_int4(rs[4], rs[5], rs[6], rs[7]);

    cudaFuncSetAttribute(ngp_mma_kernel, cudaFuncAttributeMaxDynamicSharedMemorySize, SMEM_BYTES);
    ngp_mma_kernel<<<CTAS, THREADS, SMEM_BYTES>>>(x, table, w1, w2, r1, r2, r3,
                                                  out, N, ra, rb);
}

// round 11
// speedup vs baseline: 1.0396x; 1.0396x over previous
#include <cuda_runtime.h>
#include <cuda_bf16.h>
#include <math.h>

#define THREADS 256
#define WARPS 8
#define CTAS 444

// dynamic smem byte offsets
#define OFF_TAB 0                        // 8192 bf16x2 words            (32768 B)
#define OFF_W1T 32768                    // [n=64][8w] pair layout        (2048 B)
#define OFF_R1T (OFF_W1T + 2048)         // same                          (2048 B)
#define OFF_W2T (OFF_R1T + 2048)         // [n=16][40w] pair layout       (2560 B)
#define OFF_R2T (OFF_W2T + 2560)         // [n=64][40w]                  (10240 B)
#define OFF_R3T (OFF_R2T + 10240)        // [n= 8][40w]                   (1280 B)
#define OFF_STG (OFF_R3T + 1280)         // per warp: 8 kpairs * 40 words (1280 B)
#define SMEM_BYTES (OFF_STG + WARPS * 1280)   // 61184 B

__device__ __forceinline__ unsigned pack_bf16(float lo, float hi) {
    unsigned d;
    asm("cvt.rn.bf16x2.f32 %0, %1, %2;" : "=r"(d) : "f"(hi), "f"(lo));
    return d;
}
__device__ __forceinline__ unsigned packrelu(float a, float b) {
    unsigned d = pack_bf16(a, b);
    __nv_bfloat162 z = __float2bfloat162_rn(0.f);
    __nv_bfloat162 v = __hmax2(*(__nv_bfloat162*)&d, z);
    return *(unsigned*)&v;
}
__device__ __forceinline__ void mma_bf16(float* c, const unsigned* a,
                                         unsigned b0, unsigned b1) {
    asm volatile(
        "mma.sync.aligned.m16n8k16.row.col.f32.bf16.bf16.f32 "
        "{%0,%1,%2,%3}, {%4,%5,%6,%7}, {%8,%9}, {%0,%1,%2,%3};\n"
        : "+f"(c[0]), "+f"(c[1]), "+f"(c[2]), "+f"(c[3])
        : "r"(a[0]), "r"(a[1]), "r"(a[2]), "r"(a[3]), "r"(b0), "r"(b1));
}
__device__ __forceinline__ float ldg_nc(const float* p) {
    float v;
    asm("ld.global.nc.f32 %0, [%1];" : "=f"(v) : "l"(p));
    return v;
}

// element index for k16 pair layout (w1t/r1t): word = n*8 + tig*2 + j
__device__ __forceinline__ int e_k16(int n, int k) {
    int tig = (k >> 1) & 3, j = (k >> 3) & 1;
    return (n * 8 + tig * 2 + j) * 2 + (k & 1);
}
// element index for k64 pair layout (w2t/r2t/r3t): word = n*40 + kc*8 + tig*2 + j
__device__ __forceinline__ int e_k64(int n, int k) {
    int kc = k >> 4, kk = k & 15;
    int tig = (kk >> 1) & 3, j = (kk >> 3) & 1;
    return (n * 40 + kc * 8 + tig * 2 + j) * 2 + (k & 1);
}

__global__ __launch_bounds__(THREADS, 3) void ngp_mma_kernel(
    const float* __restrict__ x,
    const float* __restrict__ table,
    const float* __restrict__ w1,
    const float* __restrict__ w2,
    const float* __restrict__ r1,
    const float* __restrict__ r2,
    const float* __restrict__ r3,
    float* __restrict__ out,
    int N, int4 ra, int4 rb)
{
    extern __shared__ char sm[];
    unsigned* s_tab = (unsigned*)(sm + OFF_TAB);       // bf16x2 per entry
    __nv_bfloat16* w1t = (__nv_bfloat16*)(sm + OFF_W1T);
    __nv_bfloat16* r1t = (__nv_bfloat16*)(sm + OFF_R1T);
    __nv_bfloat16* w2t = (__nv_bfloat16*)(sm + OFF_W2T);
    __nv_bfloat16* r2t = (__nv_bfloat16*)(sm + OFF_R2T);
    __nv_bfloat16* r3t = (__nv_bfloat16*)(sm + OFF_R3T);
    const unsigned* w1t_w = (const unsigned*)w1t;
    const unsigned* r1t_w = (const unsigned*)r1t;
    const unsigned* w2t_w = (const unsigned*)w2t;
    const unsigned* r2t_w = (const unsigned*)r2t;
    const unsigned* r3t_w = (const unsigned*)r3t;

    const int tid = threadIdx.x;
    for (int i = tid; i < 8192; i += THREADS) {
        float2 t = ((const float2*)table)[i];
        s_tab[i] = pack_bf16(t.x, t.y);
    }
    for (int i = tid; i < 1024; i += THREADS) {
        int n = i >> 4, k = i & 15;
        int e = e_k16(n, k);
        w1t[e] = __float2bfloat16(w1[k * 64 + n]);
        r1t[e] = __float2bfloat16(r1[k * 64 + n]);
    }
    for (int i = tid; i < 1024; i += THREADS) {
        int n = i >> 6, k = i & 63;
        w2t[e_k64(n, k)] = __float2bfloat16(w2[k * 16 + n]);
    }
    for (int i = tid; i < 4096; i += THREADS) {
        int n = i >> 6, k = i & 63;
        r2t[e_k64(n, k)] = __float2bfloat16(r2[k * 64 + n]);
    }
    for (int i = tid; i < 640; i += THREADS) {   // 8 rows * 40 words * 2 elems
        int word = i >> 1;
        int n = word / 40, rem = word % 40;
        int kc = rem >> 3, tig = (rem >> 1) & 3, j = rem & 1;
        int k = kc * 16 + j * 8 + tig * 2 + (i & 1);
        r3t[i] = __float2bfloat16((n == 0 && rem < 32) ? r3[k] : 0.f);
    }
    __syncthreads();

    const int res[8] = {ra.x, ra.y, ra.z, ra.w, rb.x, rb.y, rb.z, rb.w};

    const int warp = tid >> 5, lane = tid & 31;
    const int g = lane >> 2, tig = lane & 3;
    unsigned* stg = (unsigned*)(sm + OFF_STG) + warp * 320;  // 8 kpairs x 40 words

    const int gw = blockIdx.x * WARPS + warp;
    const int stride = CTAS * WARPS * 32;

    for (int base = gw * 32; base < N; base += stride) {
        __syncwarp();
        // ------------ hash-grid encode: one point per lane ------------
        int p = base + lane;
        unsigned hfp[8];
        if (p < N) {
            float x01 = ldg_nc(x + 3 * p)     + 0.5f;
            float y01 = ldg_nc(x + 3 * p + 1) + 0.5f;
            float z01 = ldg_nc(x + 3 * p + 2) + 0.5f;
            #pragma unroll
            for (int l = 0; l < 8; l++) {
                float rf = (float)res[l];
                float fx = x01 * rf, fy = y01 * rf, fz = z01 * rf;
                float gx = floorf(fx), gy = floorf(fy), gz = floorf(fz);
                float wx = fx - gx, wy = fy - gy, wz = fz - gz;
                unsigned ix = (unsigned)(int)gx;
                unsigned iy = (unsigned)(int)gy;
                unsigned iz = (unsigned)(int)gz;
                unsigned hx0 = ix, hx1 = ix + 1u;
                unsigned hy0 = iy * 2654435761u, hy1 = hy0 + 2654435761u;
                unsigned hz0 = iz * 805459861u,  hz1 = hz0 + 805459861u;
                float wx0 = 1.f - wx, wy0 = 1.f - wy, wz0 = 1.f - wz;
                float w00 = wx0 * wy0, w01 = wx0 * wy;
                float w10 = wx * wy0,  w11 = wx * wy;
                unsigned wz0d = pack_bf16(wz0, wz0);
                unsigned wz1d = pack_bf16(wz, wz);
                const unsigned* tl = s_tab + l * 1024;
                __nv_bfloat162 accA = __floats2bfloat162_rn(0.f, 0.f);
                __nv_bfloat162 accB = accA;
                // z-pair factorization: m = wz0*T0 + wz1*T1; acc += wxy*m
                #pragma unroll
                for (int c = 0; c < 4; c++) {
                    unsigned hbase = ((c & 2) ? hx1 : hx0)
                                   ^ ((c & 1) ? hy1 : hy0);
                    float wxy = (c & 2) ? ((c & 1) ? w11 : w10)
                                        : ((c & 1) ? w01 : w00);
                    unsigned idx0 = (hbase ^ hz0) & 1023u;
                    unsigned idx1 = (hbase ^ hz1) & 1023u;
                    unsigned td0 = tl[idx0];
                    unsigned td1 = tl[idx1];
                    __nv_bfloat162 m = __hmul2(*(__nv_bfloat162*)&wz0d,
                                               *(__nv_bfloat162*)&td0);
                    m = __hfma2(*(__nv_bfloat162*)&wz1d,
                                *(__nv_bfloat162*)&td1, m);
                    unsigned wxyd = pack_bf16(wxy, wxy);
                    if (c < 2)
                        accA = __hfma2(*(__nv_bfloat162*)&wxyd, m, accA);
                    else
                        accB = __hfma2(*(__nv_bfloat162*)&wxyd, m, accB);
                }
                __nv_bfloat162 acc = __hadd2(accA, accB);
                hfp[l] = *(unsigned*)&acc;
            }
        } else {
            #pragma unroll
            for (int l = 0; l < 8; l++) hfp[l] = 0u;
        }
        #pragma unroll
        for (int kp = 0; kp < 8; kp++)
            stg[kp * 40 + lane] = hfp[kp];
        __syncwarp();

        // ------------ A0 fragments for both 16-point chains ------------
        unsigned A0h0[4], A0h1[4];
        A0h0[0] = stg[tig * 40 + g];
        A0h0[1] = stg[tig * 40 + g + 8];
        A0h0[2] = stg[(tig + 4) * 40 + g];
        A0h0[3] = stg[(tig + 4) * 40 + g + 8];
        A0h1[0] = stg[tig * 40 + 16 + g];
        A0h1[1] = stg[tig * 40 + 16 + g + 8];
        A0h1[2] = stg[(tig + 4) * 40 + 16 + g];
        A0h1[3] = stg[(tig + 4) * 40 + 16 + g + 8];

        // ------------ L1+L2 fused: 16 -> 64 (relu) -> 16 ------------
        // L1 block-pair cp produces exactly the A-chunk (kc=cp) that L2
        // consumes, so A1 never materializes as a full array.
        unsigned A2h0[4], A2h1[4];
        {
            float C20h0[4] = {0,0,0,0}, C20h1[4] = {0,0,0,0};
            float C21h0[4] = {0,0,0,0}, C21h1[4] = {0,0,0,0};
            #pragma unroll
            for (int cp = 0; cp < 4; cp++) {
                float Ca0[4] = {0,0,0,0}, Ca1[4] = {0,0,0,0};
                float Cb0[4] = {0,0,0,0}, Cb1[4] = {0,0,0,0};
                int na = 16 * cp + g, nb = na + 8;
                uint2 ba = *(const uint2*)(w1t_w + na * 8 + tig * 2);
                uint2 bb = *(const uint2*)(w1t_w + nb * 8 + tig * 2);
                mma_bf16(Ca0, A0h0, ba.x, ba.y);
                mma_bf16(Ca1, A0h1, ba.x, ba.y);
                mma_bf16(Cb0, A0h0, bb.x, bb.y);
                mma_bf16(Cb1, A0h1, bb.x, bb.y);
                unsigned A1c0[4], A1c1[4];
                A1c0[0] = packrelu(Ca0[0], Ca0[1]);
                A1c0[1] = packrelu(Ca0[2], Ca0[3]);
                A1c0[2] = packrelu(Cb0[0], Cb0[1]);
                A1c0[3] = packrelu(Cb0[2], Cb0[3]);
                A1c1[0] = packrelu(Ca1[0], Ca1[1]);
                A1c1[1] = packrelu(Ca1[2], Ca1[3]);
                A1c1[2] = packrelu(Cb1[0], Cb1[1]);
                A1c1[3] = packrelu(Cb1[2], Cb1[3]);
                // L2 with k-chunk kc = cp
                uint2 b0 = *(const uint2*)(w2t_w + g * 40 + cp * 8 + tig * 2);
                uint2 b1 = *(const uint2*)(w2t_w + (8 + g) * 40 + cp * 8 + tig * 2);
                mma_bf16(C20h0, A1c0, b0.x, b0.y);
                mma_bf16(C20h1, A1c1, b0.x, b0.y);
                mma_bf16(C21h0, A1c0, b1.x, b1.y);
                mma_bf16(C21h1, A1c1, b1.x, b1.y);
            }
            A2h0[0] = pack_bf16(C20h0[0], C20h0[1]);
            A2h0[1] = pack_bf16(C20h0[2], C20h0[3]);
            A2h0[2] = pack_bf16(C21h0[0], C21h0[1]);
            A2h0[3] = pack_bf16(C21h0[2], C21h0[3]);
            A2h1[0] = pack_bf16(C20h1[0], C20h1[1]);
            A2h1[1] = pack_bf16(C20h1[2], C20h1[3]);
            A2h1[2] = pack_bf16(C21h1[0], C21h1[1]);
            A2h1[3] = pack_bf16(C21h1[2], C21h1[3]);
        }

        // ------------ L3: 16 -> 64, relu ------------
        unsigned A3h0[16], A3h1[16];
        #pragma unroll
        for (int cp = 0; cp < 4; cp++) {
            float Ca0[4] = {0,0,0,0}, Ca1[4] = {0,0,0,0};
            float Cb0[4] = {0,0,0,0}, Cb1[4] = {0,0,0,0};
            int na = 16 * cp + g, nb = na + 8;
            uint2 ba = *(const uint2*)(r1t_w + na * 8 + tig * 2);
            uint2 bb = *(const uint2*)(r1t_w + nb * 8 + tig * 2);
            mma_bf16(Ca0, A2h0, ba.x, ba.y);
            mma_bf16(Ca1, A2h1, ba.x, ba.y);
            mma_bf16(Cb0, A2h0, bb.x, bb.y);
            mma_bf16(Cb1, A2h1, bb.x, bb.y);
            A3h0[cp*4+0] = packrelu(Ca0[0], Ca0[1]);
            A3h0[cp*4+1] = packrelu(Ca0[2], Ca0[3]);
            A3h0[cp*4+2] = packrelu(Cb0[0], Cb0[1]);
            A3h0[cp*4+3] = packrelu(Cb0[2], Cb0[3]);
            A3h1[cp*4+0] = packrelu(Ca1[0], Ca1[1]);
            A3h1[cp*4+1] = packrelu(Ca1[2], Ca1[3]);
            A3h1[cp*4+2] = packrelu(Cb1[0], Cb1[1]);
            A3h1[cp*4+3] = packrelu(Cb1[2], Cb1[3]);
        }

        // ------------ L4+L5 fused: 64 -> 64 (relu) -> 1 ------------
        // L4 block-pair cp output is exactly L5's k-chunk kc = cp.
        float C5h0[4] = {0,0,0,0}, C5h1[4] = {0,0,0,0};
        #pragma unroll
        for (int cp = 0; cp < 4; cp++) {
            float Ca0[4] = {0,0,0,0}, Ca1[4] = {0,0,0,0};
            float Cb0[4] = {0,0,0,0}, Cb1[4] = {0,0,0,0};
            int na = 16 * cp + g, nb = na + 8;
            #pragma unroll
            for (int kc = 0; kc < 4; kc++) {
                uint2 ba = *(const uint2*)(r2t_w + na * 40 + kc * 8 + tig * 2);
                uint2 bb = *(const uint2*)(r2t_w + nb * 40 + kc * 8 + tig * 2);
                mma_bf16(Ca0, &A3h0[kc*4], ba.x, ba.y);
                mma_bf16(Ca1, &A3h1[kc*4], ba.x, ba.y);
                mma_bf16(Cb0, &A3h0[kc*4], bb.x, bb.y);
                mma_bf16(Cb1, &A3h1[kc*4], bb.x, bb.y);
            }
            unsigned Gc0[4], Gc1[4];
            Gc0[0] = packrelu(Ca0[0], Ca0[1]);
            Gc0[1] = packrelu(Ca0[2], Ca0[3]);
            Gc0[2] = packrelu(Cb0[0], Cb0[1]);
            Gc0[3] = packrelu(Cb0[2], Cb0[3]);
            Gc1[0] = packrelu(Ca1[0], Ca1[1]);
            Gc1[1] = packrelu(Ca1[2], Ca1[3]);
            Gc1[2] = packrelu(Cb1[0], Cb1[1]);
            Gc1[3] = packrelu(Cb1[2], Cb1[3]);
            uint2 b5 = *(const uint2*)(r3t_w + g * 40 + cp * 8 + tig * 2);
            mma_bf16(C5h0, Gc0, b5.x, b5.y);
            mma_bf16(C5h1, Gc1, b5.x, b5.y);
        }

        if (tig == 0) {
            int o = base + g;
            if (o < N)      out[o]      = 1.f / (1.f + __expf(-C5h0[0]));
            if (o + 8 < N)  out[o + 8]  = 1.f / (1.f + __expf(-C5h0[2]));
            if (o + 16 < N) out[o + 16] = 1.f / (1.f + __expf(-C5h1[0]));
            if (o + 24 < N) out[o + 24] = 1.f / (1.f + __expf(-C5h1[2]));
        }
    }
}

extern "C" void kernel_launch(void* const* d_in, const int* in_sizes, int n_in,
                              void* d_out, int out_size) {
    const float* x     = (const float*)d_in[0];
    const float* table = (const float*)d_in[1];
    const float* w1    = (const float*)d_in[2];
    const float* w2    = (const float*)d_in[3];
    const float* r1    = (const float*)d_in[4];
    const float* r2    = (const float*)d_in[5];
    const float* r3    = (const float*)d_in[6];
    float* out = (float*)d_out;
    int N = in_sizes[0] / 3;

    // Replicate numpy's RES computation with host libm (RES[7] sits at 10-1e-14).
    double b = exp(log(5.0) / 7.0);
    int rs[8];
    for (int l = 0; l < 8; l++) rs[l] = (int)floor(2.0 * pow(b, (double)l));
    int4 ra = make_int4(rs[0], rs[1], rs[2], rs[3]);
    int4 rb = make_int4(rs[4], rs[5], rs[6], rs[7]);

    cudaFuncSetAttribute(ngp_mma_kernel, cudaFuncAttributeMaxDynamicSharedMemorySize, SMEM_BYTES);
    ngp_mma_kernel<<<CTAS, THREADS, SMEM_BYTES>>>(x, table, w1, w2, r1, r2, r3,
                                                  out, N, ra, rb);
}